// round 13
// baseline (speedup 1.0000x reference)
#include <cuda_runtime.h>
#include <cstdint>

// LSTM B=4096,T=512,F=32,H=60 via int8 mma.sync.m16n8k32, base-255 2-limb.
// R13: x-path EXACT (adds Lx=A0B0 for kf0); dynamic W scale (block-reduced
// max|kernel|); bias (+forget) applied in fp32 epilogue (out of the MMA).
// gates = (255*Hh + Mh)*SCL + [(255*Hx+Mx)*255 + Lx]*SCLX + bias.
// A cols: 0..31 x (clamp +-8, scale 4064), 32..91 h (scale 32512), 92..95 0.
// Shfl-free gate layout. 256 CTAs x 16 rows, 2/SM.

#define T_STEPS 512
#define F_IN    32
#define H_DIM   60
#define ROWS    16
#define THREADS 256

#define WROWB   112
#define WROWS   240
#define WLIMB   (WROWS * WROWB)      // 26880 per W limb array
#define ALIMB   (ROWS * WROWB)       // 1792 per A limb per buffer

#define OFF_W1  0
#define OFF_W0  WLIMB                // 26880
#define OFF_A1  (2 * WLIMB)          // 53760 (2 bufs)
#define OFF_A0  (OFF_A1 + 2 * ALIMB) // 57344 (2 bufs)
#define SMEM_BYTES (OFF_A0 + 2 * ALIMB)   // 60928

#define SA_H  32512.0f
#define SA_X  4064.0f

static __device__ __forceinline__ uint32_t smem_u32(const void* p) {
    uint32_t a;
    asm("{ .reg .u64 t; cvta.to.shared.u64 t, %1; cvt.u32.u64 %0, t; }" : "=r"(a) : "l"(p));
    return a;
}
static __device__ __forceinline__ void ldsm4(uint32_t* r, uint32_t addr) {
    asm volatile("ldmatrix.sync.aligned.m8n8.x4.shared.b16 {%0,%1,%2,%3}, [%4];"
        : "=r"(r[0]), "=r"(r[1]), "=r"(r[2]), "=r"(r[3]) : "r"(addr));
}
static __device__ __forceinline__ void imma(int* d, const uint32_t* a, const uint32_t* b) {
    asm volatile("mma.sync.aligned.m16n8k32.row.col.s32.s8.s8.s32 "
        "{%0,%1,%2,%3}, {%4,%5,%6,%7}, {%8,%9}, {%0,%1,%2,%3};"
        : "+r"(d[0]), "+r"(d[1]), "+r"(d[2]), "+r"(d[3])
        : "r"(a[0]), "r"(a[1]), "r"(a[2]), "r"(a[3]), "r"(b[0]), "r"(b[1]));
}
static __device__ __forceinline__ float sigmoid_f(float x) {
    return __fdividef(1.0f, 1.0f + __expf(-x));
}
static __device__ __forceinline__ float tanh_f(float x) {
    float e = __expf(-2.0f * fabsf(x));
    float r = __fdividef(1.0f - e, 1.0f + e);
    return copysignf(r, x);
}
// base-255 balanced split; |v*scale| <= 32512 guaranteed by construction
static __device__ __forceinline__ void split255(float v, float scale, int& q1, int& q0) {
    float qf  = rintf(v * scale);
    float q1f = rintf(qf * (1.0f / 255.0f));
    q1 = (int)q1f;
    q0 = (int)(qf - 255.0f * q1f);
}

__global__ void __launch_bounds__(THREADS, 2)
lstm_i8_kernel(const float* __restrict__ x,
               const float* __restrict__ kernel,   // [92][240] cols g*60+u
               const float* __restrict__ bias,     // [240]
               const float* __restrict__ dense_w,  // [60]
               const float* __restrict__ dense_b,  // [1]
               float* __restrict__ out, int Btotal)
{
    extern __shared__ char smem[];
    const uint32_t sb = smem_u32(smem);
    const int tid = threadIdx.x, wid = tid >> 5, lane = tid & 31;
    const int row0 = blockIdx.x * ROWS;

    // ---- block-reduce max|kernel| (scratch: A region, re-zeroed after)
    float* red = (float*)(smem + OFF_A1);
    {
        float m = 0.0f;
        for (int i = tid; i < 92 * 240; i += THREADS) m = fmaxf(m, fabsf(kernel[i]));
        red[tid] = m;
        __syncthreads();
        for (int s = THREADS / 2; s > 0; s >>= 1) {
            if (tid < s) red[tid] = fmaxf(red[tid], red[tid + s]);
            __syncthreads();
        }
    }
    const float wmax = fmaxf(red[0], 1e-12f);
    __syncthreads();
    const float SB_W = 32300.0f / wmax;
    const float SCL  = 255.0f / (SA_H * SB_W);
    const float SCLX = 1.0f / (SA_X * SB_W);

    // ---- zero A limb region (both limbs, both bufs)
    for (int i = tid; i < 4 * ALIMB / 4; i += THREADS)
        ((uint32_t*)(smem + OFF_A1))[i] = 0u;

    // ---- W quantize (base-255 limbs, dynamic scale), shfl-free n-permutation.
    // n -> (g,u): w=n/32, r=n%32, F=r/8, fp=F/2, gp=F&1, j=r%8, c=j/2, g1=j&1,
    // u=8w+4fp+c, g=2*gp+g1 (gate order i,j,f,o). k>=92 zero; bias NOT here.
    for (int idx = tid; idx < WROWS * 96; idx += THREADS) {
        int n = idx / 96, k = idx - n * 96;
        int w = n >> 5, r = n & 31, F = r >> 3, j = r & 7;
        int fp = F >> 1, gp = F & 1, c = j >> 1, g1 = j & 1;
        int u = 8 * w + 4 * fp + c;
        int g = 2 * gp + g1;
        float v = (u < H_DIM && k < 92) ? kernel[k * 240 + g * 60 + u] : 0.0f;
        int q1, q0;
        split255(v, SB_W, q1, q0);
        *(int8_t*)(smem + OFF_W1 + n * WROWB + k) = (int8_t)q1;
        *(int8_t*)(smem + OFF_W0 + n * WROWB + k) = (int8_t)q0;
    }

    // ---- x mapping: thread -> (row jr = tid/16, col pair q = tid%16)
    const int jr = tid >> 4, q = tid & 15;
    const bool rowOK = (row0 + jr) < Btotal;
    const float2* xp = (const float2*)(x + (size_t)(row0 + jr) * (T_STEPS * F_IN)) + q;
    const int xoff = jr * WROWB + 2 * q;

    auto store_x = [&](float2 v, int bufo) {
        int a1, a0, b1, b0;
        split255(fminf(fmaxf(v.x, -8.f), 8.f), SA_X, a1, a0);
        split255(fminf(fmaxf(v.y, -8.f), 8.f), SA_X, b1, b0);
        *(uint16_t*)(smem + OFF_A1 + bufo + xoff) =
            (uint16_t)((a1 & 0xFF) | ((b1 & 0xFF) << 8));
        *(uint16_t*)(smem + OFF_A0 + bufo + xoff) =
            (uint16_t)((a0 & 0xFF) | ((b0 & 0xFF) << 8));
    };
    __syncthreads();
    if (rowOK) store_x(__ldg(xp), 0);
    __syncthreads();

    // ---- per-lane ldsm offsets
    const int aoff = (lane & 15) * WROWB + (lane >> 4) * 16;       // A m16k32
    const int boff = ((lane & 7) + ((lane & 16) ? 8 : 0)) * WROWB
                   + ((lane & 8) ? 16 : 0);                        // B 16 n-rows
    const int n0 = wid * 32;
    const bool have2 = (n0 + 16) < WROWS;                          // warp 7: false
    const uint32_t bW1a = sb + OFF_W1 + n0 * WROWB + boff;
    const uint32_t bW0a = sb + OFF_W0 + n0 * WROWB + boff;
    const uint32_t bW1b = bW1a + (have2 ? 16 * WROWB : 0);
    const uint32_t bW0b = bW0a + (have2 ? 16 * WROWB : 0);

    // pointwise lane constants: cell u = 8w+4fp+(lane%4), rows lane/4, +8
    const int cc = lane & 3;
    const int prow0 = lane >> 2;

    // ---- bias registers (forget bias folded into f)
    float bi[2], bj[2], bf[2], bo[2];
    {
        const int u0 = 8 * wid + cc;
        bi[0] = __ldg(&bias[u0]);
        bj[0] = __ldg(&bias[60 + u0]);
        bf[0] = __ldg(&bias[120 + u0]) + 1.0f;
        bo[0] = __ldg(&bias[180 + u0]);
        bi[1] = bj[1] = bf[1] = bo[1] = 0.0f;
        if (have2) {
            const int u1 = u0 + 4;
            bi[1] = __ldg(&bias[u1]);
            bj[1] = __ldg(&bias[60 + u1]);
            bf[1] = __ldg(&bias[120 + u1]) + 1.0f;
            bo[1] = __ldg(&bias[180 + u1]);
        }
    }

    float c_state[4], hreg[4];
#pragma unroll
    for (int i = 0; i < 4; i++) { c_state[i] = 0.0f; hreg[i] = 0.0f; }

    for (int t = 0; t < T_STEPS; ++t) {
        const int cbo = (t & 1) * ALIMB;
        const int nbo = ((t + 1) & 1) * ALIMB;

        float2 xq;
        const bool xgo = (t + 1 < T_STEPS) && rowOK;
        if (xgo) xq = __ldg(xp + (size_t)(t + 1) * (F_IN / 2));

        const uint32_t aA1 = sb + OFF_A1 + cbo + aoff;
        const uint32_t aA0 = sb + OFF_A0 + cbo + aoff;

        int accH[4][4], accM[4][4], accL[4][4];
#pragma unroll
        for (int n = 0; n < 4; n++)
#pragma unroll
            for (int e = 0; e < 4; e++) { accH[n][e] = 0; accM[n][e] = 0; accL[n][e] = 0; }

        // ---- phase 1: x chunk (kf0) — exact 3-product int8 GEMM
        {
            uint32_t A1f[4], A0f[4], B1f[8], B0f[8];
            ldsm4(A1f, aA1);
            ldsm4(A0f, aA0);
            ldsm4(B1f, bW1a);
            ldsm4(B0f, bW0a);
            if (have2) { ldsm4(B1f + 4, bW1b); ldsm4(B0f + 4, bW0b); }
            imma(accH[0], A1f, B1f + 0);
            imma(accH[1], A1f, B1f + 2);
            imma(accM[0], A1f, B0f + 0);
            imma(accM[1], A1f, B0f + 2);
            imma(accM[0], A0f, B1f + 0);
            imma(accM[1], A0f, B1f + 2);
            imma(accL[0], A0f, B0f + 0);
            imma(accL[1], A0f, B0f + 2);
            if (have2) {
                imma(accH[2], A1f, B1f + 4);
                imma(accH[3], A1f, B1f + 6);
                imma(accM[2], A1f, B0f + 4);
                imma(accM[3], A1f, B0f + 6);
                imma(accM[2], A0f, B1f + 4);
                imma(accM[3], A0f, B1f + 6);
                imma(accL[2], A0f, B0f + 4);
                imma(accL[3], A0f, B0f + 6);
            }
        }
        // fold x contribution to float, free int accs for h phase
        float xc[4][4];
#pragma unroll
        for (int n = 0; n < 4; n++)
#pragma unroll
            for (int e = 0; e < 4; e++) {
                xc[n][e] = ((float)(255 * accH[n][e] + accM[n][e]) * 255.0f
                            + (float)accL[n][e]) * SCLX;
                accH[n][e] = 0; accM[n][e] = 0;
            }

        // ---- phase 2: h chunks (kf1, kf2) — 2-limb (lo*lo dropped; tiny)
#pragma unroll
        for (int kf = 1; kf < 3; kf++) {
            const int ko = kf * 32;
            uint32_t A1f[4], A0f[4], B1f[8], B0f[8];
            ldsm4(A1f, aA1 + ko);
            ldsm4(A0f, aA0 + ko);
            ldsm4(B1f, bW1a + ko);
            ldsm4(B0f, bW0a + ko);
            if (have2) { ldsm4(B1f + 4, bW1b + ko); ldsm4(B0f + 4, bW0b + ko); }
            imma(accH[0], A1f, B1f + 0);
            imma(accH[1], A1f, B1f + 2);
            imma(accM[0], A1f, B0f + 0);
            imma(accM[1], A1f, B0f + 2);
            imma(accM[0], A0f, B1f + 0);
            imma(accM[1], A0f, B1f + 2);
            if (have2) {
                imma(accH[2], A1f, B1f + 4);
                imma(accH[3], A1f, B1f + 6);
                imma(accM[2], A1f, B0f + 4);
                imma(accM[3], A1f, B0f + 6);
                imma(accM[2], A0f, B1f + 4);
                imma(accM[3], A0f, B1f + 6);
            }
        }

        // ---- pointwise: frags (2fp, 2fp+1) = (i,j), (f,o) of cell u
        const bool last = (t == T_STEPS - 1);
#pragma unroll
        for (int fp = 0; fp < 2; fp++) {
            if (fp == 1 && !have2) break;
            const int na = 2 * fp, nb = 2 * fp + 1;
            const int u = 8 * wid + 4 * fp + cc;
#pragma unroll
            for (int rh = 0; rh < 2; rh++) {
                const int e0 = 2 * rh, e1 = 2 * rh + 1;
                float gi = (float)(255 * accH[na][e0] + accM[na][e0]) * SCL
                         + xc[na][e0] + bi[fp];
                float gj = (float)(255 * accH[na][e1] + accM[na][e1]) * SCL
                         + xc[na][e1] + bj[fp];
                float gf = (float)(255 * accH[nb][e0] + accM[nb][e0]) * SCL
                         + xc[nb][e0] + bf[fp];
                float go = (float)(255 * accH[nb][e1] + accM[nb][e1]) * SCL
                         + xc[nb][e1] + bo[fp];
                const int si = 2 * fp + rh;
                float ig = sigmoid_f(gi);
                float jg = tanh_f(gj);
                float fg = sigmoid_f(gf);
                float og = sigmoid_f(go);
                float c2 = c_state[si] * fg + ig * jg;
                c_state[si] = c2;
                float h = tanh_f(c2) * og;
                int q1, q0;
                split255(h, SA_H, q1, q0);
                const int ho = (prow0 + 8 * rh) * WROWB + 32 + u;
                *(int8_t*)(smem + OFF_A1 + nbo + ho) = (int8_t)q1;
                *(int8_t*)(smem + OFF_A0 + nbo + ho) = (int8_t)q0;
                if (last) hreg[si] = h;
            }
        }

        if (xgo) store_x(xq, nbo);

        __syncthreads();
    }

    // ---- stage final h (fp32) into dead W region, then dense
    float* Gf = (float*)smem;      // 16 x 64 f32
#pragma unroll
    for (int fp = 0; fp < 2; fp++) {
        if (fp == 1 && !have2) break;
        const int u = 8 * wid + 4 * fp + cc;
#pragma unroll
        for (int rh = 0; rh < 2; rh++)
            Gf[(prow0 + 8 * rh) * 64 + u] = hreg[2 * fp + rh];
    }
    __syncthreads();

    if (tid < ROWS && (row0 + tid) < Btotal) {
        float s = __ldg(dense_b);
        const float* hr = Gf + tid * 64;
#pragma unroll
        for (int u = 0; u < H_DIM; u++) s = fmaf(hr[u], __ldg(&dense_w[u]), s);
        out[row0 + tid] = s;
    }
}

extern "C" void kernel_launch(void* const* d_in, const int* in_sizes, int n_in,
                              void* d_out, int out_size)
{
    const float* x       = (const float*)d_in[0];
    const float* kernel  = (const float*)d_in[1];
    const float* bias    = (const float*)d_in[2];
    const float* dense_w = (const float*)d_in[3];
    const float* dense_b = (const float*)d_in[4];
    float* out = (float*)d_out;

    int Btotal = in_sizes[0] / (T_STEPS * F_IN);    // 4096
    int grid   = (Btotal + ROWS - 1) / ROWS;        // 256

    cudaFuncSetAttribute(lstm_i8_kernel,
                         cudaFuncAttributeMaxDynamicSharedMemorySize, SMEM_BYTES);

    lstm_i8_kernel<<<grid, THREADS, SMEM_BYTES>>>(
        x, kernel, bias, dense_w, dense_b, out, Btotal);
}

// round 14
// speedup vs baseline: 1.3279x; 1.3279x over previous
#include <cuda_runtime.h>
#include <cstdint>

// LSTM B=4096,T=512,F=32,H=60 via int8 mma.sync.m16n8k32, base-255 2-limb.
// R14 = R13 + hardware tanh activations (tanh.approx.f32, sm_75+ MUFU.TANH):
// sigmoid(x) = 0.5*tanh(0.5x)+0.5. Halves the MUFU pipe (was the largest
// per-step consumer at ~1280 cyc/SMSP). Quantization scheme unchanged:
// x-path exact (Hx,Mx,Lx), h-path 2-limb, dynamic W scale, fp32-epilogue bias.
// 256 CTAs x 16 rows, 2/SM. Shfl-free gate layout.

#define T_STEPS 512
#define F_IN    32
#define H_DIM   60
#define ROWS    16
#define THREADS 256

#define WROWB   112
#define WROWS   240
#define WLIMB   (WROWS * WROWB)      // 26880 per W limb array
#define ALIMB   (ROWS * WROWB)       // 1792 per A limb per buffer

#define OFF_W1  0
#define OFF_W0  WLIMB                // 26880
#define OFF_A1  (2 * WLIMB)          // 53760 (2 bufs)
#define OFF_A0  (OFF_A1 + 2 * ALIMB) // 57344 (2 bufs)
#define SMEM_BYTES (OFF_A0 + 2 * ALIMB)   // 60928

#define SA_H  32512.0f
#define SA_X  4064.0f

static __device__ __forceinline__ uint32_t smem_u32(const void* p) {
    uint32_t a;
    asm("{ .reg .u64 t; cvta.to.shared.u64 t, %1; cvt.u32.u64 %0, t; }" : "=r"(a) : "l"(p));
    return a;
}
static __device__ __forceinline__ void ldsm4(uint32_t* r, uint32_t addr) {
    asm volatile("ldmatrix.sync.aligned.m8n8.x4.shared.b16 {%0,%1,%2,%3}, [%4];"
        : "=r"(r[0]), "=r"(r[1]), "=r"(r[2]), "=r"(r[3]) : "r"(addr));
}
static __device__ __forceinline__ void imma(int* d, const uint32_t* a, const uint32_t* b) {
    asm volatile("mma.sync.aligned.m16n8k32.row.col.s32.s8.s8.s32 "
        "{%0,%1,%2,%3}, {%4,%5,%6,%7}, {%8,%9}, {%0,%1,%2,%3};"
        : "+r"(d[0]), "+r"(d[1]), "+r"(d[2]), "+r"(d[3])
        : "r"(a[0]), "r"(a[1]), "r"(a[2]), "r"(a[3]), "r"(b[0]), "r"(b[1]));
}
// hardware tanh (MUFU.TANH, 1 op); sigmoid derived (1 MUFU + 2 FMA)
static __device__ __forceinline__ float tanh_f(float x) {
    float r;
    asm("tanh.approx.f32 %0, %1;" : "=f"(r) : "f"(x));
    return r;
}
static __device__ __forceinline__ float sigmoid_f(float x) {
    return fmaf(tanh_f(0.5f * x), 0.5f, 0.5f);
}
// base-255 balanced split; |v*scale| <= 32512 guaranteed by construction
static __device__ __forceinline__ void split255(float v, float scale, int& q1, int& q0) {
    float qf  = rintf(v * scale);
    float q1f = rintf(qf * (1.0f / 255.0f));
    q1 = (int)q1f;
    q0 = (int)(qf - 255.0f * q1f);
}

__global__ void __launch_bounds__(THREADS, 2)
lstm_i8_kernel(const float* __restrict__ x,
               const float* __restrict__ kernel,   // [92][240] cols g*60+u
               const float* __restrict__ bias,     // [240]
               const float* __restrict__ dense_w,  // [60]
               const float* __restrict__ dense_b,  // [1]
               float* __restrict__ out, int Btotal)
{
    extern __shared__ char smem[];
    const uint32_t sb = smem_u32(smem);
    const int tid = threadIdx.x, wid = tid >> 5, lane = tid & 31;
    const int row0 = blockIdx.x * ROWS;

    // ---- block-reduce max|kernel| (scratch: A region, re-zeroed after)
    float* red = (float*)(smem + OFF_A1);
    {
        float m = 0.0f;
        for (int i = tid; i < 92 * 240; i += THREADS) m = fmaxf(m, fabsf(kernel[i]));
        red[tid] = m;
        __syncthreads();
        for (int s = THREADS / 2; s > 0; s >>= 1) {
            if (tid < s) red[tid] = fmaxf(red[tid], red[tid + s]);
            __syncthreads();
        }
    }
    const float wmax = fmaxf(red[0], 1e-12f);
    __syncthreads();
    const float SB_W = 32300.0f / wmax;
    const float SCL  = 255.0f / (SA_H * SB_W);
    const float SCLX = 1.0f / (SA_X * SB_W);

    // ---- zero A limb region (both limbs, both bufs)
    for (int i = tid; i < 4 * ALIMB / 4; i += THREADS)
        ((uint32_t*)(smem + OFF_A1))[i] = 0u;

    // ---- W quantize (base-255 limbs, dynamic scale), shfl-free n-permutation.
    // n -> (g,u): w=n/32, r=n%32, F=r/8, fp=F/2, gp=F&1, j=r%8, c=j/2, g1=j&1,
    // u=8w+4fp+c, g=2*gp+g1 (gate order i,j,f,o). k>=92 zero; bias NOT here.
    for (int idx = tid; idx < WROWS * 96; idx += THREADS) {
        int n = idx / 96, k = idx - n * 96;
        int w = n >> 5, r = n & 31, F = r >> 3, j = r & 7;
        int fp = F >> 1, gp = F & 1, c = j >> 1, g1 = j & 1;
        int u = 8 * w + 4 * fp + c;
        int g = 2 * gp + g1;
        float v = (u < H_DIM && k < 92) ? kernel[k * 240 + g * 60 + u] : 0.0f;
        int q1, q0;
        split255(v, SB_W, q1, q0);
        *(int8_t*)(smem + OFF_W1 + n * WROWB + k) = (int8_t)q1;
        *(int8_t*)(smem + OFF_W0 + n * WROWB + k) = (int8_t)q0;
    }

    // ---- x mapping: thread -> (row jr = tid/16, col pair q = tid%16)
    const int jr = tid >> 4, q = tid & 15;
    const bool rowOK = (row0 + jr) < Btotal;
    const float2* xp = (const float2*)(x + (size_t)(row0 + jr) * (T_STEPS * F_IN)) + q;
    const int xoff = jr * WROWB + 2 * q;

    auto store_x = [&](float2 v, int bufo) {
        int a1, a0, b1, b0;
        split255(fminf(fmaxf(v.x, -8.f), 8.f), SA_X, a1, a0);
        split255(fminf(fmaxf(v.y, -8.f), 8.f), SA_X, b1, b0);
        *(uint16_t*)(smem + OFF_A1 + bufo + xoff) =
            (uint16_t)((a1 & 0xFF) | ((b1 & 0xFF) << 8));
        *(uint16_t*)(smem + OFF_A0 + bufo + xoff) =
            (uint16_t)((a0 & 0xFF) | ((b0 & 0xFF) << 8));
    };
    __syncthreads();
    if (rowOK) store_x(__ldg(xp), 0);
    __syncthreads();

    // ---- per-lane ldsm offsets
    const int aoff = (lane & 15) * WROWB + (lane >> 4) * 16;       // A m16k32
    const int boff = ((lane & 7) + ((lane & 16) ? 8 : 0)) * WROWB
                   + ((lane & 8) ? 16 : 0);                        // B 16 n-rows
    const int n0 = wid * 32;
    const bool have2 = (n0 + 16) < WROWS;                          // warp 7: false
    const uint32_t bW1a = sb + OFF_W1 + n0 * WROWB + boff;
    const uint32_t bW0a = sb + OFF_W0 + n0 * WROWB + boff;
    const uint32_t bW1b = bW1a + (have2 ? 16 * WROWB : 0);
    const uint32_t bW0b = bW0a + (have2 ? 16 * WROWB : 0);

    // pointwise lane constants: cell u = 8w+4fp+(lane%4), rows lane/4, +8
    const int cc = lane & 3;
    const int prow0 = lane >> 2;

    // ---- bias registers (forget bias folded into f)
    float bi[2], bj[2], bf[2], bo[2];
    {
        const int u0 = 8 * wid + cc;
        bi[0] = __ldg(&bias[u0]);
        bj[0] = __ldg(&bias[60 + u0]);
        bf[0] = __ldg(&bias[120 + u0]) + 1.0f;
        bo[0] = __ldg(&bias[180 + u0]);
        bi[1] = bj[1] = bf[1] = bo[1] = 0.0f;
        if (have2) {
            const int u1 = u0 + 4;
            bi[1] = __ldg(&bias[u1]);
            bj[1] = __ldg(&bias[60 + u1]);
            bf[1] = __ldg(&bias[120 + u1]) + 1.0f;
            bo[1] = __ldg(&bias[180 + u1]);
        }
    }

    float c_state[4], hreg[4];
#pragma unroll
    for (int i = 0; i < 4; i++) { c_state[i] = 0.0f; hreg[i] = 0.0f; }

    for (int t = 0; t < T_STEPS; ++t) {
        const int cbo = (t & 1) * ALIMB;
        const int nbo = ((t + 1) & 1) * ALIMB;

        float2 xq;
        const bool xgo = (t + 1 < T_STEPS) && rowOK;
        if (xgo) xq = __ldg(xp + (size_t)(t + 1) * (F_IN / 2));

        const uint32_t aA1 = sb + OFF_A1 + cbo + aoff;
        const uint32_t aA0 = sb + OFF_A0 + cbo + aoff;

        int accH[4][4], accM[4][4], accL[4][4];
#pragma unroll
        for (int n = 0; n < 4; n++)
#pragma unroll
            for (int e = 0; e < 4; e++) { accH[n][e] = 0; accM[n][e] = 0; accL[n][e] = 0; }

        // ---- phase 1: x chunk (kf0) — exact 3-product int8 GEMM
        {
            uint32_t A1f[4], A0f[4], B1f[8], B0f[8];
            ldsm4(A1f, aA1);
            ldsm4(A0f, aA0);
            ldsm4(B1f, bW1a);
            ldsm4(B0f, bW0a);
            if (have2) { ldsm4(B1f + 4, bW1b); ldsm4(B0f + 4, bW0b); }
            imma(accH[0], A1f, B1f + 0);
            imma(accH[1], A1f, B1f + 2);
            imma(accM[0], A1f, B0f + 0);
            imma(accM[1], A1f, B0f + 2);
            imma(accM[0], A0f, B1f + 0);
            imma(accM[1], A0f, B1f + 2);
            imma(accL[0], A0f, B0f + 0);
            imma(accL[1], A0f, B0f + 2);
            if (have2) {
                imma(accH[2], A1f, B1f + 4);
                imma(accH[3], A1f, B1f + 6);
                imma(accM[2], A1f, B0f + 4);
                imma(accM[3], A1f, B0f + 6);
                imma(accM[2], A0f, B1f + 4);
                imma(accM[3], A0f, B1f + 6);
                imma(accL[2], A0f, B0f + 4);
                imma(accL[3], A0f, B0f + 6);
            }
        }
        // fold x contribution to float, free int accs for h phase
        float xc[4][4];
#pragma unroll
        for (int n = 0; n < 4; n++)
#pragma unroll
            for (int e = 0; e < 4; e++) {
                xc[n][e] = ((float)(255 * accH[n][e] + accM[n][e]) * 255.0f
                            + (float)accL[n][e]) * SCLX;
                accH[n][e] = 0; accM[n][e] = 0;
            }

        // ---- phase 2: h chunks (kf1, kf2) — 2-limb (lo*lo dropped; tiny)
#pragma unroll
        for (int kf = 1; kf < 3; kf++) {
            const int ko = kf * 32;
            uint32_t A1f[4], A0f[4], B1f[8], B0f[8];
            ldsm4(A1f, aA1 + ko);
            ldsm4(A0f, aA0 + ko);
            ldsm4(B1f, bW1a + ko);
            ldsm4(B0f, bW0a + ko);
            if (have2) { ldsm4(B1f + 4, bW1b + ko); ldsm4(B0f + 4, bW0b + ko); }
            imma(accH[0], A1f, B1f + 0);
            imma(accH[1], A1f, B1f + 2);
            imma(accM[0], A1f, B0f + 0);
            imma(accM[1], A1f, B0f + 2);
            imma(accM[0], A0f, B1f + 0);
            imma(accM[1], A0f, B1f + 2);
            if (have2) {
                imma(accH[2], A1f, B1f + 4);
                imma(accH[3], A1f, B1f + 6);
                imma(accM[2], A1f, B0f + 4);
                imma(accM[3], A1f, B0f + 6);
                imma(accM[2], A0f, B1f + 4);
                imma(accM[3], A0f, B1f + 6);
            }
        }

        // ---- pointwise: frags (2fp, 2fp+1) = (i,j), (f,o) of cell u
        const bool last = (t == T_STEPS - 1);
#pragma unroll
        for (int fp = 0; fp < 2; fp++) {
            if (fp == 1 && !have2) break;
            const int na = 2 * fp, nb = 2 * fp + 1;
            const int u = 8 * wid + 4 * fp + cc;
#pragma unroll
            for (int rh = 0; rh < 2; rh++) {
                const int e0 = 2 * rh, e1 = 2 * rh + 1;
                float gi = (float)(255 * accH[na][e0] + accM[na][e0]) * SCL
                         + xc[na][e0] + bi[fp];
                float gj = (float)(255 * accH[na][e1] + accM[na][e1]) * SCL
                         + xc[na][e1] + bj[fp];
                float gf = (float)(255 * accH[nb][e0] + accM[nb][e0]) * SCL
                         + xc[nb][e0] + bf[fp];
                float go = (float)(255 * accH[nb][e1] + accM[nb][e1]) * SCL
                         + xc[nb][e1] + bo[fp];
                const int si = 2 * fp + rh;
                float ig = sigmoid_f(gi);
                float jg = tanh_f(gj);
                float fg = sigmoid_f(gf);
                float og = sigmoid_f(go);
                float c2 = c_state[si] * fg + ig * jg;
                c_state[si] = c2;
                float h = tanh_f(c2) * og;
                int q1, q0;
                split255(h, SA_H, q1, q0);
                const int ho = (prow0 + 8 * rh) * WROWB + 32 + u;
                *(int8_t*)(smem + OFF_A1 + nbo + ho) = (int8_t)q1;
                *(int8_t*)(smem + OFF_A0 + nbo + ho) = (int8_t)q0;
                if (last) hreg[si] = h;
            }
        }

        if (xgo) store_x(xq, nbo);

        __syncthreads();
    }

    // ---- stage final h (fp32) into dead W region, then dense
    float* Gf = (float*)smem;      // 16 x 64 f32
#pragma unroll
    for (int fp = 0; fp < 2; fp++) {
        if (fp == 1 && !have2) break;
        const int u = 8 * wid + 4 * fp + cc;
#pragma unroll
        for (int rh = 0; rh < 2; rh++)
            Gf[(prow0 + 8 * rh) * 64 + u] = hreg[2 * fp + rh];
    }
    __syncthreads();

    if (tid < ROWS && (row0 + tid) < Btotal) {
        float s = __ldg(dense_b);
        const float* hr = Gf + tid * 64;
#pragma unroll
        for (int u = 0; u < H_DIM; u++) s = fmaf(hr[u], __ldg(&dense_w[u]), s);
        out[row0 + tid] = s;
    }
}

extern "C" void kernel_launch(void* const* d_in, const int* in_sizes, int n_in,
                              void* d_out, int out_size)
{
    const float* x       = (const float*)d_in[0];
    const float* kernel  = (const float*)d_in[1];
    const float* bias    = (const float*)d_in[2];
    const float* dense_w = (const float*)d_in[3];
    const float* dense_b = (const float*)d_in[4];
    float* out = (float*)d_out;

    int Btotal = in_sizes[0] / (T_STEPS * F_IN);    // 4096
    int grid   = (Btotal + ROWS - 1) / ROWS;        // 256

    cudaFuncSetAttribute(lstm_i8_kernel,
                         cudaFuncAttributeMaxDynamicSharedMemorySize, SMEM_BYTES);

    lstm_i8_kernel<<<grid, THREADS, SMEM_BYTES>>>(
        x, kernel, bias, dense_w, dense_b, out, Btotal);
}

// round 16
// speedup vs baseline: 1.4001x; 1.0543x over previous
#include <cuda_runtime.h>
#include <cstdint>

// LSTM B=4096,T=512,F=32,H=60 via int8 mma.sync.m16n8k32, base-256 2-limb.
// R16 = R14 + (a) base-256 limb splits (pure-int split/recombine, one cvt.rni;
// s8 holds -128 so q0 in [-128,127] is legal), (b) all A-fragment ldsm hoisted
// to the top of each step so LDS latency overlaps phase-1 immas.
// x-path exact (Hx,Mx,Lx), h-path 2-limb, dynamic W scale, fp32-epilogue bias,
// hardware tanh activations. 256 CTAs x 16 rows, 2/SM. Shfl-free gate layout.

#define T_STEPS 512
#define F_IN    32
#define H_DIM   60
#define ROWS    16
#define THREADS 256

#define WROWB   112
#define WROWS   240
#define WLIMB   (WROWS * WROWB)      // 26880 per W limb array
#define ALIMB   (ROWS * WROWB)       // 1792 per A limb per buffer

#define OFF_W1  0
#define OFF_W0  WLIMB                // 26880
#define OFF_A1  (2 * WLIMB)          // 53760 (2 bufs)
#define OFF_A0  (OFF_A1 + 2 * ALIMB) // 57344 (2 bufs)
#define SMEM_BYTES (OFF_A0 + 2 * ALIMB)   // 60928

#define SA_H  32512.0f
#define SA_X  4064.0f

static __device__ __forceinline__ uint32_t smem_u32(const void* p) {
    uint32_t a;
    asm("{ .reg .u64 t; cvta.to.shared.u64 t, %1; cvt.u32.u64 %0, t; }" : "=r"(a) : "l"(p));
    return a;
}
static __device__ __forceinline__ void ldsm4(uint32_t* r, uint32_t addr) {
    asm volatile("ldmatrix.sync.aligned.m8n8.x4.shared.b16 {%0,%1,%2,%3}, [%4];"
        : "=r"(r[0]), "=r"(r[1]), "=r"(r[2]), "=r"(r[3]) : "r"(addr));
}
static __device__ __forceinline__ void imma(int* d, const uint32_t* a, const uint32_t* b) {
    asm volatile("mma.sync.aligned.m16n8k32.row.col.s32.s8.s8.s32 "
        "{%0,%1,%2,%3}, {%4,%5,%6,%7}, {%8,%9}, {%0,%1,%2,%3};"
        : "+r"(d[0]), "+r"(d[1]), "+r"(d[2]), "+r"(d[3])
        : "r"(a[0]), "r"(a[1]), "r"(a[2]), "r"(a[3]), "r"(b[0]), "r"(b[1]));
}
// hardware tanh (MUFU.TANH); sigmoid derived (1 MUFU + 2 FMA)
static __device__ __forceinline__ float tanh_f(float x) {
    float r;
    asm("tanh.approx.f32 %0, %1;" : "=f"(r) : "f"(x));
    return r;
}
static __device__ __forceinline__ float sigmoid_f(float x) {
    return fmaf(tanh_f(0.5f * x), 0.5f, 0.5f);
}
// round-to-nearest int
static __device__ __forceinline__ int f2i_rn(float v) {
    int r;
    asm("cvt.rni.s32.f32 %0, %1;" : "=r"(r) : "f"(v));
    return r;
}
// base-256 split: q = 256*q1 + q0, q1 in [-127,127], q0 in [-128,127]
static __device__ __forceinline__ void split256(float v, float scale, int& q1, int& q0) {
    int qi = f2i_rn(v * scale);
    q1 = (qi + 128) >> 8;
    q0 = qi - (q1 << 8);
}

__global__ void __launch_bounds__(THREADS, 2)
lstm_i8_kernel(const float* __restrict__ x,
               const float* __restrict__ kernel,   // [92][240] cols g*60+u
               const float* __restrict__ bias,     // [240]
               const float* __restrict__ dense_w,  // [60]
               const float* __restrict__ dense_b,  // [1]
               float* __restrict__ out, int Btotal)
{
    extern __shared__ char smem[];
    const uint32_t sb = smem_u32(smem);
    const int tid = threadIdx.x, wid = tid >> 5, lane = tid & 31;
    const int row0 = blockIdx.x * ROWS;

    // ---- block-reduce max|kernel| (scratch: A region, re-zeroed after)
    float* red = (float*)(smem + OFF_A1);
    {
        float m = 0.0f;
        for (int i = tid; i < 92 * 240; i += THREADS) m = fmaxf(m, fabsf(kernel[i]));
        red[tid] = m;
        __syncthreads();
        for (int s = THREADS / 2; s > 0; s >>= 1) {
            if (tid < s) red[tid] = fmaxf(red[tid], red[tid + s]);
            __syncthreads();
        }
    }
    const float wmax = fmaxf(red[0], 1e-12f);
    __syncthreads();
    const float SB_W = 32600.0f / wmax;
    const float SCL  = 256.0f / (SA_H * SB_W);
    const float SCLX = 1.0f / (SA_X * SB_W);

    // ---- zero A limb region (both limbs, both bufs)
    for (int i = tid; i < 4 * ALIMB / 4; i += THREADS)
        ((uint32_t*)(smem + OFF_A1))[i] = 0u;

    // ---- W quantize (base-256 limbs, dynamic scale), shfl-free n-permutation.
    // n -> (g,u): w=n/32, r=n%32, F=r/8, fp=F/2, gp=F&1, j=r%8, c=j/2, g1=j&1,
    // u=8w+4fp+c, g=2*gp+g1 (gate order i,j,f,o). k>=92 zero; bias NOT here.
    for (int idx = tid; idx < WROWS * 96; idx += THREADS) {
        int n = idx / 96, k = idx - n * 96;
        int w = n >> 5, r = n & 31, F = r >> 3, j = r & 7;
        int fp = F >> 1, gp = F & 1, c = j >> 1, g1 = j & 1;
        int u = 8 * w + 4 * fp + c;
        int g = 2 * gp + g1;
        float v = (u < H_DIM && k < 92) ? kernel[k * 240 + g * 60 + u] : 0.0f;
        int q1, q0;
        split256(v, SB_W, q1, q0);
        *(int8_t*)(smem + OFF_W1 + n * WROWB + k) = (int8_t)q1;
        *(int8_t*)(smem + OFF_W0 + n * WROWB + k) = (int8_t)q0;
    }

    // ---- x mapping: thread -> (row jr = tid/16, col pair q = tid%16)
    const int jr = tid >> 4, q = tid & 15;
    const bool rowOK = (row0 + jr) < Btotal;
    const float2* xp = (const float2*)(x + (size_t)(row0 + jr) * (T_STEPS * F_IN)) + q;
    const int xoff = jr * WROWB + 2 * q;

    auto store_x = [&](float2 v, int bufo) {
        int a1, a0, b1, b0;
        split256(fminf(fmaxf(v.x, -8.f), 8.f), SA_X, a1, a0);
        split256(fminf(fmaxf(v.y, -8.f), 8.f), SA_X, b1, b0);
        *(uint16_t*)(smem + OFF_A1 + bufo + xoff) =
            (uint16_t)((a1 & 0xFF) | ((b1 & 0xFF) << 8));
        *(uint16_t*)(smem + OFF_A0 + bufo + xoff) =
            (uint16_t)((a0 & 0xFF) | ((b0 & 0xFF) << 8));
    };
    __syncthreads();
    if (rowOK) store_x(__ldg(xp), 0);
    __syncthreads();

    // ---- per-lane ldsm offsets
    const int aoff = (lane & 15) * WROWB + (lane >> 4) * 16;       // A m16k32
    const int boff = ((lane & 7) + ((lane & 16) ? 8 : 0)) * WROWB
                   + ((lane & 8) ? 16 : 0);                        // B 16 n-rows
    const int n0 = wid * 32;
    const bool have2 = (n0 + 16) < WROWS;                          // warp 7: false
    const uint32_t bW1a = sb + OFF_W1 + n0 * WROWB + boff;
    const uint32_t bW0a = sb + OFF_W0 + n0 * WROWB + boff;
    const uint32_t bW1b = bW1a + (have2 ? 16 * WROWB : 0);
    const uint32_t bW0b = bW0a + (have2 ? 16 * WROWB : 0);

    // pointwise lane constants: cell u = 8w+4fp+(lane%4), rows lane/4, +8
    const int cc = lane & 3;
    const int prow0 = lane >> 2;

    // ---- bias registers (forget bias folded into f)
    float bi[2], bj[2], bf[2], bo[2];
    {
        const int u0 = 8 * wid + cc;
        bi[0] = __ldg(&bias[u0]);
        bj[0] = __ldg(&bias[60 + u0]);
        bf[0] = __ldg(&bias[120 + u0]) + 1.0f;
        bo[0] = __ldg(&bias[180 + u0]);
        bi[1] = bj[1] = bf[1] = bo[1] = 0.0f;
        if (have2) {
            const int u1 = u0 + 4;
            bi[1] = __ldg(&bias[u1]);
            bj[1] = __ldg(&bias[60 + u1]);
            bf[1] = __ldg(&bias[120 + u1]) + 1.0f;
            bo[1] = __ldg(&bias[180 + u1]);
        }
    }

    float c_state[4], hreg[4];
#pragma unroll
    for (int i = 0; i < 4; i++) { c_state[i] = 0.0f; hreg[i] = 0.0f; }

    for (int t = 0; t < T_STEPS; ++t) {
        const int cbo = (t & 1) * ALIMB;
        const int nbo = ((t + 1) & 1) * ALIMB;

        float2 xq;
        const bool xgo = (t + 1 < T_STEPS) && rowOK;
        if (xgo) xq = __ldg(xp + (size_t)(t + 1) * (F_IN / 2));

        const uint32_t aA1 = sb + OFF_A1 + cbo + aoff;
        const uint32_t aA0 = sb + OFF_A0 + cbo + aoff;

        // ---- hoist ALL A-fragment loads (latency overlaps phase-1 immas)
        uint32_t A1f[3][4], A0f[3][4];
#pragma unroll
        for (int kf = 0; kf < 3; kf++) {
            ldsm4(A1f[kf], aA1 + kf * 32);
            ldsm4(A0f[kf], aA0 + kf * 32);
        }

        int accH[4][4], accM[4][4], accL[4][4];
#pragma unroll
        for (int n = 0; n < 4; n++)
#pragma unroll
            for (int e = 0; e < 4; e++) { accH[n][e] = 0; accM[n][e] = 0; accL[n][e] = 0; }

        // ---- phase 1: x chunk (kf0) — exact 3-product int8 GEMM
        {
            uint32_t B1f[8], B0f[8];
            ldsm4(B1f, bW1a);
            ldsm4(B0f, bW0a);
            if (have2) { ldsm4(B1f + 4, bW1b); ldsm4(B0f + 4, bW0b); }
            imma(accH[0], A1f[0], B1f + 0);
            imma(accH[1], A1f[0], B1f + 2);
            imma(accM[0], A1f[0], B0f + 0);
            imma(accM[1], A1f[0], B0f + 2);
            imma(accM[0], A0f[0], B1f + 0);
            imma(accM[1], A0f[0], B1f + 2);
            imma(accL[0], A0f[0], B0f + 0);
            imma(accL[1], A0f[0], B0f + 2);
            if (have2) {
                imma(accH[2], A1f[0], B1f + 4);
                imma(accH[3], A1f[0], B1f + 6);
                imma(accM[2], A1f[0], B0f + 4);
                imma(accM[3], A1f[0], B0f + 6);
                imma(accM[2], A0f[0], B1f + 4);
                imma(accM[3], A0f[0], B1f + 6);
                imma(accL[2], A0f[0], B0f + 4);
                imma(accL[3], A0f[0], B0f + 6);
            }
        }
        // fold x contribution to float, free int accs for h phase
        float xc[4][4];
#pragma unroll
        for (int n = 0; n < 4; n++)
#pragma unroll
            for (int e = 0; e < 4; e++) {
                xc[n][e] = ((float)((accH[n][e] << 8) + accM[n][e]) * 256.0f
                            + (float)accL[n][e]) * SCLX;
                accH[n][e] = 0; accM[n][e] = 0;
            }

        // ---- phase 2: h chunks (kf1, kf2) — 2-limb (lo*lo dropped; tiny)
#pragma unroll
        for (int kf = 1; kf < 3; kf++) {
            const int ko = kf * 32;
            uint32_t B1f[8], B0f[8];
            ldsm4(B1f, bW1a + ko);
            ldsm4(B0f, bW0a + ko);
            if (have2) { ldsm4(B1f + 4, bW1b + ko); ldsm4(B0f + 4, bW0b + ko); }
            imma(accH[0], A1f[kf], B1f + 0);
            imma(accH[1], A1f[kf], B1f + 2);
            imma(accM[0], A1f[kf], B0f + 0);
            imma(accM[1], A1f[kf], B0f + 2);
            imma(accM[0], A0f[kf], B1f + 0);
            imma(accM[1], A0f[kf], B1f + 2);
            if (have2) {
                imma(accH[2], A1f[kf], B1f + 4);
                imma(accH[3], A1f[kf], B1f + 6);
                imma(accM[2], A1f[kf], B0f + 4);
                imma(accM[3], A1f[kf], B0f + 6);
                imma(accM[2], A0f[kf], B1f + 4);
                imma(accM[3], A0f[kf], B1f + 6);
            }
        }

        // ---- pointwise: frags (2fp, 2fp+1) = (i,j), (f,o) of cell u
        const bool last = (t == T_STEPS - 1);
#pragma unroll
        for (int fp = 0; fp < 2; fp++) {
            if (fp == 1 && !have2) break;
            const int na = 2 * fp, nb = 2 * fp + 1;
            const int u = 8 * wid + 4 * fp + cc;
#pragma unroll
            for (int rh = 0; rh < 2; rh++) {
                const int e0 = 2 * rh, e1 = 2 * rh + 1;
                float gi = (float)((accH[na][e0] << 8) + accM[na][e0]) * SCL
                         + xc[na][e0] + bi[fp];
                float gj = (float)((accH[na][e1] << 8) + accM[na][e1]) * SCL
                         + xc[na][e1] + bj[fp];
                float gf = (float)((accH[nb][e0] << 8) + accM[nb][e0]) * SCL
                         + xc[nb][e0] + bf[fp];
                float go = (float)((accH[nb][e1] << 8) + accM[nb][e1]) * SCL
                         + xc[nb][e1] + bo[fp];
                const int si = 2 * fp + rh;
                float ig = sigmoid_f(gi);
                float jg = tanh_f(gj);
                float fg = sigmoid_f(gf);
                float og = sigmoid_f(go);
                float c2 = c_state[si] * fg + ig * jg;
                c_state[si] = c2;
                float h = tanh_f(c2) * og;
                int q1, q0;
                split256(h, SA_H, q1, q0);
                const int ho = (prow0 + 8 * rh) * WROWB + 32 + u;
                *(int8_t*)(smem + OFF_A1 + nbo + ho) = (int8_t)q1;
                *(int8_t*)(smem + OFF_A0 + nbo + ho) = (int8_t)q0;
                if (last) hreg[si] = h;
            }
        }

        if (xgo) store_x(xq, nbo);

        __syncthreads();
    }

    // ---- stage final h (fp32) into dead W region, then dense
    float* Gf = (float*)smem;      // 16 x 64 f32
#pragma unroll
    for (int fp = 0; fp < 2; fp++) {
        if (fp == 1 && !have2) break;
        const int u = 8 * wid + 4 * fp + cc;
#pragma unroll
        for (int rh = 0; rh < 2; rh++)
            Gf[(prow0 + 8 * rh) * 64 + u] = hreg[2 * fp + rh];
    }
    __syncthreads();

    if (tid < ROWS && (row0 + tid) < Btotal) {
        float s = __ldg(dense_b);
        const float* hr = Gf + tid * 64;
#pragma unroll
        for (int u = 0; u < H_DIM; u++) s = fmaf(hr[u], __ldg(&dense_w[u]), s);
        out[row0 + tid] = s;
    }
}

extern "C" void kernel_launch(void* const* d_in, const int* in_sizes, int n_in,
                              void* d_out, int out_size)
{
    const float* x       = (const float*)d_in[0];
    const float* kernel  = (const float*)d_in[1];
    const float* bias    = (const float*)d_in[2];
    const float* dense_w = (const float*)d_in[3];
    const float* dense_b = (const float*)d_in[4];
    float* out = (float*)d_out;

    int Btotal = in_sizes[0] / (T_STEPS * F_IN);    // 4096
    int grid   = (Btotal + ROWS - 1) / ROWS;        // 256

    cudaFuncSetAttribute(lstm_i8_kernel,
                         cudaFuncAttributeMaxDynamicSharedMemorySize, SMEM_BYTES);

    lstm_i8_kernel<<<grid, THREADS, SMEM_BYTES>>>(
        x, kernel, bias, dense_w, dense_b, out, Btotal);
}